// round 6
// baseline (speedup 1.0000x reference)
#include <cuda_runtime.h>
#include <math.h>
#include <stdint.h>

// ---------------- problem constants ----------------
#define D1      512
#define D2      1024
#define SEQLEN  4096
#define CHUNK   256
#define NCHUNK  16
#define BATCH   4
#define NROWS   (BATCH*CHUNK)          // 1024
#define TOTROWS (BATCH*SEQLEN)         // 16384
#define LOSS_SCALE (2.0f/((float)NROWS*(float)D1))

// ---------------- device scratch ----------------
__device__ float g_W1 [D1*D2];
__device__ float g_W2 [D2*D1];
__device__ float g_S1 [D1*D2];
__device__ float g_S2 [D2*D1];
__device__ float g_WKV[D1*D2];
__device__ float g_kv [NROWS*D2];
__device__ float g_h  [NROWS*D2];
__device__ float g_a  [NROWS*D2];
__device__ float g_dp [NROWS*D1];
__device__ float g_dh [NROWS*D2];
__device__ float g_q  [TOTROWS*D1];
__device__ float g_aq [TOTROWS*D2];

// ---------------- math helpers ----------------
__device__ __forceinline__ float gelu_f(float x) {
    return 0.5f * x * (1.0f + erff(x * 0.70710678118654752f));
}
__device__ __forceinline__ float gelu_grad(float x) {
    float cdf = 0.5f * (1.0f + erff(x * 0.70710678118654752f));
    float pdf = 0.3989422804014327f * expf(-0.5f * x * x);
    return cdf + x * pdf;
}
__device__ __forceinline__ float sigmoid_f(float x) { return 1.0f / (1.0f + expf(-x)); }

// split fp32 into two tf32 values (hi + lo ~22 mantissa bits)
__device__ __forceinline__ uint2 split_tf32(float v) {
    uint32_t hi, lo;
    asm("cvt.rna.tf32.f32 %0, %1;" : "=r"(hi) : "f"(v));
    float lf = v - __uint_as_float(hi);
    asm("cvt.rna.tf32.f32 %0, %1;" : "=r"(lo) : "f"(lf));
    return make_uint2(hi, lo);
}

__device__ __forceinline__ void mma_tf32(float* c,
                                         uint32_t a0, uint32_t a1, uint32_t a2, uint32_t a3,
                                         uint32_t b0, uint32_t b1) {
    asm volatile(
        "mma.sync.aligned.m16n8k8.row.col.f32.tf32.tf32.f32 "
        "{%0,%1,%2,%3}, {%4,%5,%6,%7}, {%8,%9}, {%0,%1,%2,%3};"
        : "+f"(c[0]), "+f"(c[1]), "+f"(c[2]), "+f"(c[3])
        : "r"(a0), "r"(a1), "r"(a2), "r"(a3), "r"(b0), "r"(b1));
}

// ---------------- init ----------------
__global__ void init_kernel(const float* __restrict__ mw1, const float* __restrict__ mw2,
                            const float* __restrict__ wk,  const float* __restrict__ wv) {
    int i = blockIdx.x * blockDim.x + threadIdx.x;
    if (i < D1 * D2) {
        g_W1[i] = mw1[i];  g_S1[i] = 0.0f;
        g_W2[i] = mw2[i];  g_S2[i] = 0.0f;
        int d = i / D2, j = i % D2;
        g_WKV[i] = (j < D1) ? wk[d * D1 + j] : wv[d * D1 + (j - D1)];
    }
}

// ---------------- tensor-core GEMM (3xTF32), hi/lo pre-split in SMEM ----------------
// op(A)[M,K] * op(B)[K,N]; EPI as before:
// 0 C=acc | 1 C=acc, aux3=gelu(acc) | 2 C=(acc-aux1)*LOSS_SCALE
// 3 C=acc*gelu'(aux1) | 4 S=decay*S-lr*acc; W=(1-a)W+S | 5 C=gelu(acc)
#define BM 64
#define BN 64
#define BK 32
#define APITCH 36   // uint2 per A row  (stride 72 words: 8 mod 32 -> conflict-free LDS.64)
#define BPITCH 68   // uint2 per B row  (stride 136 words: 8 mod 32 -> conflict-free LDS.64)

template<bool TA, bool TB, int EPI>
__global__ __launch_bounds__(256)
void gemm_k(const float* __restrict__ A, const float* __restrict__ B,
            float* __restrict__ C,
            int M, int N, int K, int lda, int ldb, int ldc, int ldaux,
            long long strideA, long long strideC,
            const float* __restrict__ aux1, float* __restrict__ aux3, float* __restrict__ aux4,
            const float* __restrict__ p_alpha, const float* __restrict__ p_lr,
            const float* __restrict__ p_decay) {
    __shared__ __align__(16) uint2 As2[BM][APITCH];  // {hi,lo} per element, m-major
    __shared__ __align__(16) uint2 Bs2[BK][BPITCH];  // {hi,lo} per element, k-major

    const float* Ab = A + (size_t)blockIdx.z * strideA;
    float* Cb = C + (size_t)blockIdx.z * strideC;

    const int row0 = blockIdx.y * BM;
    const int col0 = blockIdx.x * BN;
    const int t    = threadIdx.x;
    const int lane = t & 31;
    const int warp = t >> 5;            // 0..7
    const int mW   = (warp >> 2) * 32;  // warp tile: 32 x 16, grid 2 x 4
    const int nW   = (warp & 3) * 16;
    const int g    = lane >> 2;         // 0..7
    const int t4   = lane & 3;          // 0..3

    float acc[2][2][4];
    #pragma unroll
    for (int i = 0; i < 2; i++)
        #pragma unroll
        for (int j = 0; j < 2; j++)
            #pragma unroll
            for (int r = 0; r < 4; r++) acc[i][j][r] = 0.0f;

    for (int k0 = 0; k0 < K; k0 += BK) {
        // ---- stage A (BM x BK = 2048 elems, 512 float4 over 256 thr x 2) ----
        #pragma unroll
        for (int it = 0; it < 2; it++) {
            int f = t + it * 256;
            if constexpr (!TA) {
                int m = f >> 3, kk0 = (f & 7) * 4;
                float4 v = *reinterpret_cast<const float4*>(&Ab[(size_t)(row0 + m) * lda + (k0 + kk0)]);
                uint2 s0 = split_tf32(v.x), s1 = split_tf32(v.y);
                uint2 s2 = split_tf32(v.z), s3 = split_tf32(v.w);
                *reinterpret_cast<uint4*>(&As2[m][kk0])     = make_uint4(s0.x, s0.y, s1.x, s1.y);
                *reinterpret_cast<uint4*>(&As2[m][kk0 + 2]) = make_uint4(s2.x, s2.y, s3.x, s3.y);
            } else {
                int m0 = (f & 15) * 4, kk = f >> 4;
                float4 v = *reinterpret_cast<const float4*>(&Ab[(size_t)(k0 + kk) * lda + (row0 + m0)]);
                As2[m0 + 0][kk] = split_tf32(v.x);
                As2[m0 + 1][kk] = split_tf32(v.y);
                As2[m0 + 2][kk] = split_tf32(v.z);
                As2[m0 + 3][kk] = split_tf32(v.w);
            }
        }
        // ---- stage B (BK x BN = 2048 elems) ----
        #pragma unroll
        for (int it = 0; it < 2; it++) {
            int f = t + it * 256;
            if constexpr (!TB) {
                int n0 = (f & 15) * 4, kk = f >> 4;
                float4 v = *reinterpret_cast<const float4*>(&B[(size_t)(k0 + kk) * ldb + (col0 + n0)]);
                uint2 s0 = split_tf32(v.x), s1 = split_tf32(v.y);
                uint2 s2 = split_tf32(v.z), s3 = split_tf32(v.w);
                *reinterpret_cast<uint4*>(&Bs2[kk][n0])     = make_uint4(s0.x, s0.y, s1.x, s1.y);
                *reinterpret_cast<uint4*>(&Bs2[kk][n0 + 2]) = make_uint4(s2.x, s2.y, s3.x, s3.y);
            } else {
                int kk0 = (f & 7) * 4, n = f >> 3;
                float4 v = *reinterpret_cast<const float4*>(&B[(size_t)(col0 + n) * ldb + (k0 + kk0)]);
                Bs2[kk0 + 0][n] = split_tf32(v.x);
                Bs2[kk0 + 1][n] = split_tf32(v.y);
                Bs2[kk0 + 2][n] = split_tf32(v.z);
                Bs2[kk0 + 3][n] = split_tf32(v.w);
            }
        }
        __syncthreads();

        // ---- consume: 4 k-steps of 8 ----
        #pragma unroll
        for (int ks = 0; ks < 4; ks++) {
            const int kc = ks * 8 + t4;
            uint2 a[2][4], b[2][2];
            #pragma unroll
            for (int i = 0; i < 2; i++) {
                const int mB = mW + i * 16;
                a[i][0] = As2[mB + g    ][kc    ];
                a[i][1] = As2[mB + g + 8][kc    ];
                a[i][2] = As2[mB + g    ][kc + 4];
                a[i][3] = As2[mB + g + 8][kc + 4];
            }
            #pragma unroll
            for (int j = 0; j < 2; j++) {
                const int nB = nW + j * 8 + g;
                b[j][0] = Bs2[kc    ][nB];
                b[j][1] = Bs2[kc + 4][nB];
            }
            // hi*hi
            #pragma unroll
            for (int i = 0; i < 2; i++)
                #pragma unroll
                for (int j = 0; j < 2; j++)
                    mma_tf32(acc[i][j], a[i][0].x, a[i][1].x, a[i][2].x, a[i][3].x,
                             b[j][0].x, b[j][1].x);
            // hi*lo
            #pragma unroll
            for (int i = 0; i < 2; i++)
                #pragma unroll
                for (int j = 0; j < 2; j++)
                    mma_tf32(acc[i][j], a[i][0].x, a[i][1].x, a[i][2].x, a[i][3].x,
                             b[j][0].y, b[j][1].y);
            // lo*hi
            #pragma unroll
            for (int i = 0; i < 2; i++)
                #pragma unroll
                for (int j = 0; j < 2; j++)
                    mma_tf32(acc[i][j], a[i][0].y, a[i][1].y, a[i][2].y, a[i][3].y,
                             b[j][0].x, b[j][1].x);
        }
        __syncthreads();
    }

    float alpha = 0.f, lr = 0.f, decay = 0.f;
    if constexpr (EPI == 4) {
        alpha = sigmoid_f(*p_alpha);
        lr    = sigmoid_f(*p_lr);
        decay = sigmoid_f(*p_decay);
    }

    // ---- epilogue ----
    #pragma unroll
    for (int i = 0; i < 2; i++) {
        const int rA = row0 + mW + i * 16 + g;
        #pragma unroll
        for (int j = 0; j < 2; j++) {
            const int cA = col0 + nW + j * 8 + 2 * t4;
            #pragma unroll
            for (int r = 0; r < 4; r++) {
                const int m = rA + (r >= 2 ? 8 : 0);
                const int n = cA + (r & 1);
                const size_t ci = (size_t)m * ldc + n;
                const float v = acc[i][j][r];
                if constexpr (EPI == 0) {
                    Cb[ci] = v;
                } else if constexpr (EPI == 1) {
                    Cb[ci] = v;
                    aux3[ci] = gelu_f(v);
                } else if constexpr (EPI == 2) {
                    Cb[ci] = (v - aux1[(size_t)m * ldaux + n]) * LOSS_SCALE;
                } else if constexpr (EPI == 3) {
                    Cb[ci] = v * gelu_grad(aux1[(size_t)m * ldaux + n]);
                } else if constexpr (EPI == 4) {
                    float s = decay * aux3[ci] - lr * v;
                    aux3[ci] = s;
                    aux4[ci] = (1.0f - alpha) * aux4[ci] + s;
                } else if constexpr (EPI == 5) {
                    Cb[ci] = gelu_f(v);
                }
            }
        }
    }
}

// ---------------- host driver ----------------
extern "C" void kernel_launch(void* const* d_in, const int* in_sizes, int n_in,
                              void* d_out, int out_size) {
    const float* x     = (const float*)d_in[0];
    const float* w_q   = (const float*)d_in[1];
    const float* w_k   = (const float*)d_in[2];
    const float* w_v   = (const float*)d_in[3];
    const float* mw1   = (const float*)d_in[4];
    const float* mw2   = (const float*)d_in[5];
    const float* p_al  = (const float*)d_in[6];
    const float* p_lr  = (const float*)d_in[7];
    const float* p_dec = (const float*)d_in[8];
    float* out = (float*)d_out;

    float *W1, *W2, *S1, *S2, *WKV, *KV, *H, *Abuf, *DP, *DH, *Q, *AQ;
    cudaGetSymbolAddress((void**)&W1,   g_W1);
    cudaGetSymbolAddress((void**)&W2,   g_W2);
    cudaGetSymbolAddress((void**)&S1,   g_S1);
    cudaGetSymbolAddress((void**)&S2,   g_S2);
    cudaGetSymbolAddress((void**)&WKV,  g_WKV);
    cudaGetSymbolAddress((void**)&KV,   g_kv);
    cudaGetSymbolAddress((void**)&H,    g_h);
    cudaGetSymbolAddress((void**)&Abuf, g_a);
    cudaGetSymbolAddress((void**)&DP,   g_dp);
    cudaGetSymbolAddress((void**)&DH,   g_dh);
    cudaGetSymbolAddress((void**)&Q,    g_q);
    cudaGetSymbolAddress((void**)&AQ,   g_aq);

    init_kernel<<<(D1 * D2 + 255) / 256, 256>>>(mw1, mw2, w_k, w_v);

    for (int c = 0; c < NCHUNK; c++) {
        const float* chunk = x + (size_t)c * CHUNK * D1;

        // kv = chunk @ [w_k|w_v]
        gemm_k<false, false, 0><<<dim3(D2 / BN, CHUNK / BM, BATCH), 256>>>(
            chunk, WKV, KV, CHUNK, D2, D1, D1, D2, D2, 0,
            (long long)SEQLEN * D1, (long long)CHUNK * D2,
            nullptr, nullptr, nullptr, nullptr, nullptr, nullptr);

        // h = k @ W1 ; a = gelu(h)
        gemm_k<false, false, 1><<<dim3(D2 / BN, NROWS / BM, 1), 256>>>(
            KV, W1, H, NROWS, D2, D1, D2, D2, D2, 0, 0, 0,
            nullptr, Abuf, nullptr, nullptr, nullptr, nullptr);

        // dpred = (a @ W2 - v) * 2/(N*D)
        gemm_k<false, false, 2><<<dim3(D1 / BN, NROWS / BM, 1), 256>>>(
            Abuf, W2, DP, NROWS, D1, D2, D2, D1, D1, D2, 0, 0,
            KV + D1, nullptr, nullptr, nullptr, nullptr, nullptr);

        // dh = (dpred @ W2^T) * gelu'(h)
        gemm_k<false, true, 3><<<dim3(D2 / BN, NROWS / BM, 1), 256>>>(
            DP, W2, DH, NROWS, D2, D1, D1, D1, D2, D2, 0, 0,
            H, nullptr, nullptr, nullptr, nullptr, nullptr);

        // g1 = k^T @ dh ; fused S1/W1 update
        gemm_k<true, false, 4><<<dim3(D2 / BN, D1 / BM, 1), 256>>>(
            KV, DH, nullptr, D1, D2, NROWS, D2, D2, D2, 0, 0, 0,
            nullptr, S1, W1, p_al, p_lr, p_dec);

        // g2 = a^T @ dpred ; fused S2/W2 update
        gemm_k<true, false, 4><<<dim3(D1 / BN, D2 / BM, 1), 256>>>(
            Abuf, DP, nullptr, D2, D1, NROWS, D2, D1, D1, 0, 0, 0,
            nullptr, S2, W2, p_al, p_lr, p_dec);
    }

    // q = x @ w_q
    gemm_k<false, false, 0><<<dim3(D1 / BN, TOTROWS / BM, 1), 256>>>(
        x, w_q, Q, TOTROWS, D1, D1, D1, D1, D1, 0, 0, 0,
        nullptr, nullptr, nullptr, nullptr, nullptr, nullptr);

    // aq = gelu(q @ W1)
    gemm_k<false, false, 5><<<dim3(D2 / BN, TOTROWS / BM, 1), 256>>>(
        Q, W1, AQ, TOTROWS, D2, D1, D1, D2, D2, 0, 0, 0,
        nullptr, nullptr, nullptr, nullptr, nullptr, nullptr);

    // out = aq @ W2
    gemm_k<false, false, 0><<<dim3(D1 / BN, TOTROWS / BM, 1), 256>>>(
        AQ, W2, out, TOTROWS, D1, D2, D2, D1, D1, 0, 0, 0,
        nullptr, nullptr, nullptr, nullptr, nullptr, nullptr);
}

// round 7
// speedup vs baseline: 1.4724x; 1.4724x over previous
#include <cuda_runtime.h>
#include <math.h>
#include <stdint.h>

// ---------------- problem constants ----------------
#define D1      512
#define D2      1024
#define SEQLEN  4096
#define CHUNK   256
#define NCHUNK  16
#define BATCH   4
#define NROWS   (BATCH*CHUNK)          // 1024 rows per chunk
#define TOTROWS (BATCH*SEQLEN)         // 16384
#define LOSS_SCALE (2.0f/((float)NROWS*(float)D1))

// ---------------- device scratch ----------------
__device__ float g_W1 [D1*D2];
__device__ float g_W2 [D2*D1];
__device__ float g_S1 [D1*D2];
__device__ float g_S2 [D2*D1];
__device__ float g_WKV[D1*D2];
__device__ float g_kv [NCHUNK*NROWS*D2];   // chunk-major: [c][b][r][D2], cols 0..511=k, 512..1023=v
__device__ float g_h  [NROWS*D2];
__device__ float g_a  [NROWS*D2];
__device__ float g_dp [NROWS*D1];
__device__ float g_dh [NROWS*D2];
__device__ float g_q  [TOTROWS*D1];
__device__ float g_aq [TOTROWS*D2];

// ---------------- math helpers ----------------
__device__ __forceinline__ float gelu_f(float x) {
    return 0.5f * x * (1.0f + erff(x * 0.70710678118654752f));
}
__device__ __forceinline__ float gelu_grad(float x) {
    float cdf = 0.5f * (1.0f + erff(x * 0.70710678118654752f));
    float pdf = 0.3989422804014327f * expf(-0.5f * x * x);
    return cdf + x * pdf;
}
__device__ __forceinline__ float sigmoid_f(float x) { return 1.0f / (1.0f + expf(-x)); }

__device__ __forceinline__ void split_tf32(float v, uint32_t& hi, uint32_t& lo) {
    uint32_t h;
    asm("cvt.rna.tf32.f32 %0, %1;" : "=r"(h) : "f"(v));
    float lf = v - __uint_as_float(h);
    asm("cvt.rna.tf32.f32 %0, %1;" : "=r"(lo) : "f"(lf));
    hi = h;
}
__device__ __forceinline__ void mma_tf32(float* c, const uint32_t* a, const uint32_t* b) {
    asm volatile(
        "mma.sync.aligned.m16n8k8.row.col.f32.tf32.tf32.f32 "
        "{%0,%1,%2,%3}, {%4,%5,%6,%7}, {%8,%9}, {%0,%1,%2,%3};"
        : "+f"(c[0]), "+f"(c[1]), "+f"(c[2]), "+f"(c[3])
        : "r"(a[0]), "r"(a[1]), "r"(a[2]), "r"(a[3]), "r"(b[0]), "r"(b[1]));
}

// cp.async helpers
__device__ __forceinline__ void cp16(void* s, const void* g) {
    uint32_t sa = (uint32_t)__cvta_generic_to_shared(s);
    asm volatile("cp.async.ca.shared.global [%0], [%1], 16;\n" :: "r"(sa), "l"(g));
}
__device__ __forceinline__ void cp4(void* s, const void* g) {
    uint32_t sa = (uint32_t)__cvta_generic_to_shared(s);
    asm volatile("cp.async.ca.shared.global [%0], [%1], 4;\n" :: "r"(sa), "l"(g));
}
#define CP_COMMIT() asm volatile("cp.async.commit_group;\n" ::: "memory")
#define CP_WAIT(n)  asm volatile("cp.async.wait_group %0;\n" :: "n"(n) : "memory")

// ---------------- init ----------------
__global__ void init_kernel(const float* __restrict__ mw1, const float* __restrict__ mw2,
                            const float* __restrict__ wk,  const float* __restrict__ wv) {
    int i = blockIdx.x * blockDim.x + threadIdx.x;
    if (i < D1 * D2) {
        g_W1[i] = mw1[i];  g_S1[i] = 0.0f;
        g_W2[i] = mw2[i];  g_S2[i] = 0.0f;
        int d = i / D2, j = i % D2;
        g_WKV[i] = (j < D1) ? wk[d * D1 + j] : wv[d * D1 + (j - D1)];
    }
}

// ---------------- tiling ----------------
#define BM 64
#define BN 64
#define BK 32
#define APAD 4   // A row = 36 words
#define BPAD 8   // B row = 72 words

// ---------------- generic GEMM: 3xTF32, cp.async double buffer ----------------
// EPI: 0 C=acc | 1 C=acc, aux3=gelu(acc) | 2 C=(acc-aux1)*LOSS_SCALE
//      3 C=acc*gelu'(aux1) | 5 C=gelu(acc) | 6 C[permute(m)]=acc (kv chunk-major)
template<bool TA, bool TB, int EPI>
__global__ __launch_bounds__(128)
void gemm_k(const float* __restrict__ A, const float* __restrict__ B,
            float* __restrict__ C,
            int M, int N, int K, int lda, int ldb, int ldc, int ldaux,
            const float* __restrict__ aux1, float* __restrict__ aux3) {
    __shared__ float As[2][BM][BK + APAD];
    __shared__ float Bs[2][BK][BN + BPAD];

    const int row0 = blockIdx.y * BM;
    const int col0 = blockIdx.x * BN;
    const int t    = threadIdx.x;
    const int lane = t & 31;
    const int warp = t >> 5;
    const int warpRow = (warp >> 1) * 32;
    const int warpCol = (warp & 1) * 32;
    const int g  = lane >> 2;
    const int t4 = lane & 3;

    auto stage = [&](int b, int k0) {
        #pragma unroll
        for (int it = 0; it < 4; it++) {
            int f = t + it * 128;
            if constexpr (!TA) {
                int m = f >> 3, kk0 = (f & 7) * 4;
                cp16(&As[b][m][kk0], &A[(size_t)(row0 + m) * lda + (k0 + kk0)]);
            } else {
                int m0 = (f & 15) * 4, kk = f >> 4;
                const float* src = &A[(size_t)(k0 + kk) * lda + (row0 + m0)];
                cp4(&As[b][m0 + 0][kk], src + 0);
                cp4(&As[b][m0 + 1][kk], src + 1);
                cp4(&As[b][m0 + 2][kk], src + 2);
                cp4(&As[b][m0 + 3][kk], src + 3);
            }
        }
        #pragma unroll
        for (int it = 0; it < 4; it++) {
            int f = t + it * 128;
            if constexpr (!TB) {
                int n0 = (f & 15) * 4, kk = f >> 4;
                cp16(&Bs[b][kk][n0], &B[(size_t)(k0 + kk) * ldb + (col0 + n0)]);
            } else {
                int kk0 = (f & 7) * 4, n = f >> 3;
                const float* src = &B[(size_t)(col0 + n) * ldb + (k0 + kk0)];
                cp4(&Bs[b][kk0 + 0][n], src + 0);
                cp4(&Bs[b][kk0 + 1][n], src + 1);
                cp4(&Bs[b][kk0 + 2][n], src + 2);
                cp4(&Bs[b][kk0 + 3][n], src + 3);
            }
        }
    };

    float acc[2][4][4];
    #pragma unroll
    for (int i = 0; i < 2; i++)
        #pragma unroll
        for (int j = 0; j < 4; j++)
            #pragma unroll
            for (int r = 0; r < 4; r++) acc[i][j][r] = 0.0f;

    const int KITER = K / BK;
    stage(0, 0);
    CP_COMMIT();
    int buf = 0;
    for (int it = 0; it < KITER; ++it) {
        if (it + 1 < KITER) {
            stage(buf ^ 1, (it + 1) * BK);
            CP_COMMIT();
            CP_WAIT(1);
        } else {
            CP_WAIT(0);
        }
        __syncthreads();

        #pragma unroll
        for (int ks = 0; ks < 4; ks++) {
            const int kc = ks * 8 + t4;
            uint32_t ah[2][4], al[2][4], bh[4][2], bl[4][2];
            #pragma unroll
            for (int i = 0; i < 2; i++) {
                const int mB = warpRow + i * 16;
                split_tf32(As[buf][mB + g    ][kc    ], ah[i][0], al[i][0]);
                split_tf32(As[buf][mB + g + 8][kc    ], ah[i][1], al[i][1]);
                split_tf32(As[buf][mB + g    ][kc + 4], ah[i][2], al[i][2]);
                split_tf32(As[buf][mB + g + 8][kc + 4], ah[i][3], al[i][3]);
            }
            #pragma unroll
            for (int j = 0; j < 4; j++) {
                const int nB = warpCol + j * 8 + g;
                split_tf32(Bs[buf][kc    ][nB], bh[j][0], bl[j][0]);
                split_tf32(Bs[buf][kc + 4][nB], bh[j][1], bl[j][1]);
            }
            #pragma unroll
            for (int i = 0; i < 2; i++)
                #pragma unroll
                for (int j = 0; j < 4; j++) mma_tf32(acc[i][j], ah[i], bh[j]);
            #pragma unroll
            for (int i = 0; i < 2; i++)
                #pragma unroll
                for (int j = 0; j < 4; j++) mma_tf32(acc[i][j], ah[i], bl[j]);
            #pragma unroll
            for (int i = 0; i < 2; i++)
                #pragma unroll
                for (int j = 0; j < 4; j++) mma_tf32(acc[i][j], al[i], bh[j]);
        }
        __syncthreads();
        buf ^= 1;
    }

    // ---- epilogue ----
    #pragma unroll
    for (int i = 0; i < 2; i++) {
        const int rA = row0 + warpRow + i * 16 + g;
        #pragma unroll
        for (int j = 0; j < 4; j++) {
            const int cA = col0 + warpCol + j * 8 + 2 * t4;
            #pragma unroll
            for (int r = 0; r < 4; r++) {
                const int m = rA + (r >= 2 ? 8 : 0);
                const int n = cA + (r & 1);
                const size_t ci = (size_t)m * ldc + n;
                const float v = acc[i][j][r];
                if constexpr (EPI == 0) {
                    C[ci] = v;
                } else if constexpr (EPI == 1) {
                    C[ci] = v;
                    aux3[ci] = gelu_f(v);
                } else if constexpr (EPI == 2) {
                    C[ci] = (v - aux1[(size_t)m * ldaux + n]) * LOSS_SCALE;
                } else if constexpr (EPI == 3) {
                    C[ci] = v * gelu_grad(aux1[(size_t)m * ldaux + n]);
                } else if constexpr (EPI == 5) {
                    C[ci] = gelu_f(v);
                } else if constexpr (EPI == 6) {
                    // m = b*4096 + c*256 + r  ->  out row = (c*BATCH + b)*256 + r
                    int bb = m >> 12;
                    int cc = (m >> 8) & (NCHUNK - 1);
                    int rr = m & (CHUNK - 1);
                    size_t orow = ((size_t)(cc * BATCH + bb) << 8) + rr;
                    C[orow * ldc + n] = v;
                }
            }
        }
    }
}

// ---------------- fused g1+g2 kernel (TA=true, TB=false, momentum+decay epilogue) ----------------
struct GDesc {
    const float* A;   // [K x lda] (transposed access)
    const float* B;   // [K x ldb]
    float* S;         // momentum  [M x ld]
    float* W;         // weights   [M x ld]
    int K, lda, ldb, ld, gx, gy;
};

__global__ __launch_bounds__(128)
void grad_dual_k(GDesc d0, GDesc d1,
                 const float* __restrict__ p_alpha, const float* __restrict__ p_lr,
                 const float* __restrict__ p_decay) {
    __shared__ float As[2][BM][BK + APAD];
    __shared__ float Bs[2][BK][BN + BPAD];

    const GDesc d = (blockIdx.z == 0) ? d0 : d1;
    if ((int)blockIdx.x >= d.gx || (int)blockIdx.y >= d.gy) return;

    const int row0 = blockIdx.y * BM;
    const int col0 = blockIdx.x * BN;
    const int t    = threadIdx.x;
    const int lane = t & 31;
    const int warp = t >> 5;
    const int warpRow = (warp >> 1) * 32;
    const int warpCol = (warp & 1) * 32;
    const int g  = lane >> 2;
    const int t4 = lane & 3;

    auto stage = [&](int b, int k0) {
        #pragma unroll
        for (int it = 0; it < 4; it++) {
            int f = t + it * 128;
            int m0 = (f & 15) * 4, kk = f >> 4;
            const float* src = &d.A[(size_t)(k0 + kk) * d.lda + (row0 + m0)];
            cp4(&As[b][m0 + 0][kk], src + 0);
            cp4(&As[b][m0 + 1][kk], src + 1);
            cp4(&As[b][m0 + 2][kk], src + 2);
            cp4(&As[b][m0 + 3][kk], src + 3);
        }
        #pragma unroll
        for (int it = 0; it < 4; it++) {
            int f = t + it * 128;
            int n0 = (f & 15) * 4, kk = f >> 4;
            cp16(&Bs[b][kk][n0], &d.B[(size_t)(k0 + kk) * d.ldb + (col0 + n0)]);
        }
    };

    float acc[2][4][4];
    #pragma unroll
    for (int i = 0; i < 2; i++)
        #pragma unroll
        for (int j = 0; j < 4; j++)
            #pragma unroll
            for (int r = 0; r < 4; r++) acc[i][j][r] = 0.0f;

    const int KITER = d.K / BK;
    stage(0, 0);
    CP_COMMIT();
    int buf = 0;
    for (int it = 0; it < KITER; ++it) {
        if (it + 1 < KITER) {
            stage(buf ^ 1, (it + 1) * BK);
            CP_COMMIT();
            CP_WAIT(1);
        } else {
            CP_WAIT(0);
        }
        __syncthreads();

        #pragma unroll
        for (int ks = 0; ks < 4; ks++) {
            const int kc = ks * 8 + t4;
            uint32_t ah[2][4], al[2][4], bh[4][2], bl[4][2];
            #pragma unroll
            for (int i = 0; i < 2; i++) {
                const int mB = warpRow + i * 16;
                split_tf32(As[buf][mB + g    ][kc    ], ah[i][0], al[i][0]);
                split_tf32(As[buf][mB + g + 8][kc    ], ah[i][1], al[i][1]);
                split_tf32(As[buf][mB + g    ][kc + 4], ah[i][2], al[i][2]);
                split_tf32(As[buf][mB + g + 8][kc + 4], ah[i][3], al[i][3]);
            }
            #pragma unroll
            for (int j = 0; j < 4; j++) {
                const int nB = warpCol + j * 8 + g;
                split_tf32(Bs[buf][kc    ][nB], bh[j][0], bl[j][0]);
                split_tf32(Bs[buf][kc + 4][nB], bh[j][1], bl[j][1]);
            }
            #pragma unroll
            for (int i = 0; i < 2; i++)
                #pragma unroll
                for (int j = 0; j < 4; j++) mma_tf32(acc[i][j], ah[i], bh[j]);
            #pragma unroll
            for (int i = 0; i < 2; i++)
                #pragma unroll
                for (int j = 0; j < 4; j++) mma_tf32(acc[i][j], ah[i], bl[j]);
            #pragma unroll
            for (int i = 0; i < 2; i++)
                #pragma unroll
                for (int j = 0; j < 4; j++) mma_tf32(acc[i][j], al[i], bh[j]);
        }
        __syncthreads();
        buf ^= 1;
    }

    const float alpha = sigmoid_f(*p_alpha);
    const float lr    = sigmoid_f(*p_lr);
    const float decay = sigmoid_f(*p_decay);

    #pragma unroll
    for (int i = 0; i < 2; i++) {
        const int rA = row0 + warpRow + i * 16 + g;
        #pragma unroll
        for (int j = 0; j < 4; j++) {
            const int cA = col0 + warpCol + j * 8 + 2 * t4;
            #pragma unroll
            for (int r = 0; r < 4; r++) {
                const int m = rA + (r >= 2 ? 8 : 0);
                const int n = cA + (r & 1);
                const size_t ci = (size_t)m * d.ld + n;
                float s = decay * d.S[ci] - lr * acc[i][j][r];
                d.S[ci] = s;
                d.W[ci] = (1.0f - alpha) * d.W[ci] + s;
            }
        }
    }
}

// ---------------- host driver ----------------
extern "C" void kernel_launch(void* const* d_in, const int* in_sizes, int n_in,
                              void* d_out, int out_size) {
    const float* x     = (const float*)d_in[0];
    const float* w_q   = (const float*)d_in[1];
    const float* w_k   = (const float*)d_in[2];
    const float* w_v   = (const float*)d_in[3];
    const float* mw1   = (const float*)d_in[4];
    const float* mw2   = (const float*)d_in[5];
    const float* p_al  = (const float*)d_in[6];
    const float* p_lr  = (const float*)d_in[7];
    const float* p_dec = (const float*)d_in[8];
    float* out = (float*)d_out;

    float *W1, *W2, *S1, *S2, *WKV, *KV, *H, *Abuf, *DP, *DH, *Q, *AQ;
    cudaGetSymbolAddress((void**)&W1,   g_W1);
    cudaGetSymbolAddress((void**)&W2,   g_W2);
    cudaGetSymbolAddress((void**)&S1,   g_S1);
    cudaGetSymbolAddress((void**)&S2,   g_S2);
    cudaGetSymbolAddress((void**)&WKV,  g_WKV);
    cudaGetSymbolAddress((void**)&KV,   g_kv);
    cudaGetSymbolAddress((void**)&H,    g_h);
    cudaGetSymbolAddress((void**)&Abuf, g_a);
    cudaGetSymbolAddress((void**)&DP,   g_dp);
    cudaGetSymbolAddress((void**)&DH,   g_dh);
    cudaGetSymbolAddress((void**)&Q,    g_q);
    cudaGetSymbolAddress((void**)&AQ,   g_aq);

    init_kernel<<<(D1 * D2 + 255) / 256, 256>>>(mw1, mw2, w_k, w_v);

    // ALL chunks' kv in one chip-filling GEMM, chunk-major permuted output
    gemm_k<false, false, 6><<<dim3(D2 / BN, TOTROWS / BM), 128>>>(
        x, WKV, KV, TOTROWS, D2, D1, D1, D2, D2, 0, nullptr, nullptr);

    // q = x @ w_q (independent of the chain; issue early)
    gemm_k<false, false, 0><<<dim3(D1 / BN, TOTROWS / BM), 128>>>(
        x, w_q, Q, TOTROWS, D1, D1, D1, D1, D1, 0, nullptr, nullptr);

    for (int c = 0; c < NCHUNK; c++) {
        const float* KVc = KV + (size_t)c * NROWS * D2;

        // h = k @ W1 ; a = gelu(h)
        gemm_k<false, false, 1><<<dim3(D2 / BN, NROWS / BM), 128>>>(
            KVc, W1, H, NROWS, D2, D1, D2, D2, D2, 0, nullptr, Abuf);

        // dpred = (a @ W2 - v) * 2/(N*D)
        gemm_k<false, false, 2><<<dim3(D1 / BN, NROWS / BM), 128>>>(
            Abuf, W2, DP, NROWS, D1, D2, D2, D1, D1, D2, KVc + D1, nullptr);

        // dh = (dpred @ W2^T) * gelu'(h)
        gemm_k<false, true, 3><<<dim3(D2 / BN, NROWS / BM), 128>>>(
            DP, W2, DH, NROWS, D2, D1, D1, D1, D2, D2, H, nullptr);

        // fused: g1 = k^T @ dh -> S1/W1 update ; g2 = a^T @ dpred -> S2/W2 update
        GDesc dg1 = { KVc,  DH, S1, W1, NROWS, D2, D2, D2, D2 / BN, D1 / BM };
        GDesc dg2 = { Abuf, DP, S2, W2, NROWS, D2, D1, D1, D1 / BN, D2 / BM };
        grad_dual_k<<<dim3(D2 / BN, D2 / BM, 2), 128>>>(dg1, dg2, p_al, p_lr, p_dec);
    }

    // aq = gelu(q @ W1)
    gemm_k<false, false, 5><<<dim3(D2 / BN, TOTROWS / BM), 128>>>(
        Q, W1, AQ, TOTROWS, D2, D1, D1, D2, D2, 0, nullptr, nullptr);

    // out = aq @ W2
    gemm_k<false, false, 0><<<dim3(D1 / BN, TOTROWS / BM), 128>>>(
        AQ, W2, out, TOTROWS, D1, D2, D2, D1, D1, 0, nullptr, nullptr);
}